// round 1
// baseline (speedup 1.0000x reference)
#include <cuda_runtime.h>

#define C_NUM 100000
#define D_NUM 256
#define B_NUM 1024
#define EPSV 1e-12f

__device__ float g_xnorm[B_NUM * D_NUM];
__device__ float g_winv[C_NUM];
__device__ int   g_next[B_NUM];
__device__ int   g_head[B_NUM];

__device__ __forceinline__ unsigned f2tf(float f) {
    unsigned u;
    asm("cvt.rna.tf32.f32 %0, %1;" : "=r"(u) : "f"(f));
    return u;
}

__device__ __forceinline__ void mma_tf32(float d[4], const unsigned a[4], const unsigned b[2]) {
    asm volatile(
        "mma.sync.aligned.m16n8k8.row.col.f32.tf32.tf32.f32 "
        "{%0,%1,%2,%3}, {%4,%5,%6,%7}, {%8,%9}, {%0,%1,%2,%3};\n"
        : "+f"(d[0]), "+f"(d[1]), "+f"(d[2]), "+f"(d[3])
        : "r"(a[0]), "r"(a[1]), "r"(a[2]), "r"(a[3]),
          "r"(b[0]), "r"(b[1]));
}

// ---------------------------------------------------------------------------
// K1: normalize input rows (exact fp32), write targets as float
// ---------------------------------------------------------------------------
__global__ void k_xnorm(const float* __restrict__ x, const int* __restrict__ tgt,
                        float* __restrict__ out_t) {
    int b = blockIdx.x, t = threadIdx.x;
    float v = x[b * D_NUM + t];
    float ss = v * v;
    #pragma unroll
    for (int o = 16; o; o >>= 1) ss += __shfl_xor_sync(0xffffffffu, ss, o);
    __shared__ float ws[8];
    if ((t & 31) == 0) ws[t >> 5] = ss;
    __syncthreads();
    float tot = 0.f;
    #pragma unroll
    for (int i = 0; i < 8; ++i) tot += ws[i];
    float inv = 1.f / fmaxf(sqrtf(tot), EPSV);
    g_xnorm[b * D_NUM + t] = v * inv;
    if (t == 0) out_t[b] = (float)tgt[b];
}

// ---------------------------------------------------------------------------
// K2: per-class inverse norm of W + copy W into new_weight output region
// one warp per class row (256 floats = 64 float4)
// ---------------------------------------------------------------------------
__global__ void k_winv_copy(const float4* __restrict__ w4, float4* __restrict__ nw4) {
    int gw = (blockIdx.x * blockDim.x + threadIdx.x) >> 5;
    int lane = threadIdx.x & 31;
    if (gw >= C_NUM) return;
    const float4* row = w4 + (size_t)gw * 64;
    float4 a = row[lane];
    float4 b = row[lane + 32];
    float ss = a.x*a.x + a.y*a.y + a.z*a.z + a.w*a.w
             + b.x*b.x + b.y*b.y + b.z*b.z + b.w*b.w;
    #pragma unroll
    for (int o = 16; o; o >>= 1) ss += __shfl_xor_sync(0xffffffffu, ss, o);
    float4* orow = nw4 + (size_t)gw * 64;
    orow[lane] = a;
    orow[lane + 32] = b;
    if (lane == 0) g_winv[gw] = 1.f / fmaxf(sqrtf(ss), EPSV);
}

// ---------------------------------------------------------------------------
// K3: build per-class occurrence chains (head flags + next links)
// ---------------------------------------------------------------------------
__global__ void k_chain(const int* __restrict__ tgt) {
    __shared__ int st[B_NUM];
    int i = threadIdx.x;
    st[i] = tgt[i];
    g_next[i] = -1;
    __syncthreads();
    int prev = -1;
    int me = st[i];
    for (int j = i - 1; j >= 0; --j)
        if (st[j] == me) { prev = j; break; }
    g_head[i] = (prev < 0) ? 1 : 0;
    __syncthreads();
    if (prev >= 0) g_next[prev] = i;
}

// ---------------------------------------------------------------------------
// K4: GEMM  predicts[b][c] = 30 * winv[c] * sum_d xnorm[b][d]*W[c][d]
// TF32 mma.sync, BM=BN=128, BK=32, 256 threads (2x4 warp grid, 64x32 per warp)
// ---------------------------------------------------------------------------
__global__ __launch_bounds__(256, 2)
void k_gemm(const float* __restrict__ W, float* __restrict__ out) {
    __shared__ unsigned As[128][36];  // [m][k] padded (+4) -> conflict-free
    __shared__ unsigned Bs[128][36];  // [n][k]
    const int tid = threadIdx.x;
    const int lane = tid & 31, warp = tid >> 5;
    const int b0 = blockIdx.x * 128;   // batch tile (x fastest => W tile reuse in L2)
    const int c0 = blockIdx.y * 128;   // class tile
    const int wm = (warp & 1) * 64;
    const int wn = (warp >> 1) * 32;

    float acc[4][4][4];
    #pragma unroll
    for (int i = 0; i < 4; ++i)
        #pragma unroll
        for (int j = 0; j < 4; ++j)
            #pragma unroll
            for (int r = 0; r < 4; ++r) acc[i][j][r] = 0.f;

    for (int kt = 0; kt < D_NUM; kt += 32) {
        #pragma unroll
        for (int it = 0; it < 4; ++it) {
            int v = tid + it * 256;            // float4 slot 0..1023
            int r = v >> 3, c4 = (v & 7) * 4;  // row 0..127, col 0..28
            float4 fa = *(const float4*)&g_xnorm[(size_t)(b0 + r) * D_NUM + kt + c4];
            As[r][c4 + 0] = f2tf(fa.x); As[r][c4 + 1] = f2tf(fa.y);
            As[r][c4 + 2] = f2tf(fa.z); As[r][c4 + 3] = f2tf(fa.w);
            int n = c0 + r;
            float4 fb = make_float4(0.f, 0.f, 0.f, 0.f);
            if (n < C_NUM) fb = *(const float4*)&W[(size_t)n * D_NUM + kt + c4];
            Bs[r][c4 + 0] = f2tf(fb.x); Bs[r][c4 + 1] = f2tf(fb.y);
            Bs[r][c4 + 2] = f2tf(fb.z); Bs[r][c4 + 3] = f2tf(fb.w);
        }
        __syncthreads();
        const int g4 = lane >> 2, t4 = lane & 3;
        #pragma unroll
        for (int ks = 0; ks < 4; ++ks) {
            const int k0 = ks * 8;
            unsigned af[4][4], bf[4][2];
            #pragma unroll
            for (int im = 0; im < 4; ++im) {
                int rb = wm + im * 16;
                af[im][0] = As[rb + g4][k0 + t4];
                af[im][1] = As[rb + g4 + 8][k0 + t4];
                af[im][2] = As[rb + g4][k0 + t4 + 4];
                af[im][3] = As[rb + g4 + 8][k0 + t4 + 4];
            }
            #pragma unroll
            for (int jn = 0; jn < 4; ++jn) {
                int nb = wn + jn * 8;
                bf[jn][0] = Bs[nb + g4][k0 + t4];
                bf[jn][1] = Bs[nb + g4][k0 + t4 + 4];
            }
            #pragma unroll
            for (int im = 0; im < 4; ++im)
                #pragma unroll
                for (int jn = 0; jn < 4; ++jn)
                    mma_tf32(acc[im][jn], af[im], bf[jn]);
        }
        __syncthreads();
    }

    // epilogue: scale by 30 * winv[c], store float2 pairs
    const int g4 = lane >> 2, t4 = lane & 3;
    #pragma unroll
    for (int im = 0; im < 4; ++im) {
        int row = b0 + wm + im * 16 + g4;
        #pragma unroll
        for (int jn = 0; jn < 4; ++jn) {
            int col = c0 + wn + jn * 8 + t4 * 2;
            if (col < C_NUM) {
                float2 iv = *(const float2*)&g_winv[col];
                float s0 = 30.0f * iv.x, s1 = 30.0f * iv.y;
                float2 o0 = make_float2(acc[im][jn][0] * s0, acc[im][jn][1] * s1);
                float2 o1 = make_float2(acc[im][jn][2] * s0, acc[im][jn][3] * s1);
                *(float2*)&out[(size_t)row * C_NUM + col] = o0;
                *(float2*)&out[(size_t)(row + 8) * C_NUM + col] = o1;
            }
        }
    }
}

// ---------------------------------------------------------------------------
// K5: sequential momentum update per class chain (one block per chain head)
// ---------------------------------------------------------------------------
__global__ void k_update(const int* __restrict__ tgt, float* __restrict__ nw) {
    int b = blockIdx.x;
    if (!g_head[b]) return;
    int t = threadIdx.x;
    int y = tgt[b];
    float v = nw[(size_t)y * D_NUM + t];  // raw weight copy
    __shared__ float ws[8];
    int cur = b;
    while (cur >= 0) {
        v = 0.5f * v + 0.5f * g_xnorm[cur * D_NUM + t];
        float ss = v * v;
        #pragma unroll
        for (int o = 16; o; o >>= 1) ss += __shfl_xor_sync(0xffffffffu, ss, o);
        __syncthreads();
        if ((t & 31) == 0) ws[t >> 5] = ss;
        __syncthreads();
        float tot = 0.f;
        #pragma unroll
        for (int i = 0; i < 8; ++i) tot += ws[i];
        v *= 1.f / fmaxf(sqrtf(tot), EPSV);
        cur = g_next[cur];
    }
    nw[(size_t)y * D_NUM + t] = v;
}

// ---------------------------------------------------------------------------
extern "C" void kernel_launch(void* const* d_in, const int* in_sizes, int n_in,
                              void* d_out, int out_size) {
    const float* x   = (const float*)d_in[0];
    const int*   tgt = (const int*)d_in[1];
    const float* w   = (const float*)d_in[2];
    float* out      = (float*)d_out;
    float* out_pred = out;                                  // [1024][100000]
    float* out_t    = out + (size_t)B_NUM * C_NUM;          // [1024]
    float* out_nw   = out_t + B_NUM;                        // [100000][256]

    k_xnorm<<<B_NUM, 256>>>(x, tgt, out_t);
    k_winv_copy<<<(C_NUM * 32) / 256, 256>>>((const float4*)w, (float4*)out_nw);
    k_chain<<<1, B_NUM>>>(tgt);
    k_gemm<<<dim3(8, 782), 256>>>(w, out_pred);
    k_update<<<B_NUM, 256>>>(tgt, out_nw);
}

// round 3
// speedup vs baseline: 1.4173x; 1.4173x over previous
#include <cuda_runtime.h>
#include <cstdint>

#define C_NUM 100000
#define D_NUM 256
#define B_NUM 1024
#define EPSV 1e-12f

__device__ float g_xnorm[B_NUM * D_NUM];   // tf32-rounded normalized x
__device__ float g_xexact[B_NUM * D_NUM];  // exact normalized x
__device__ float g_winv[C_NUM];
__device__ int   g_next[B_NUM];
__device__ int   g_head[B_NUM];

__device__ __forceinline__ uint32_t smem_u32(const void* p) {
    uint32_t a;
    asm("{ .reg .u64 t; cvta.to.shared.u64 t, %1; cvt.u32.u64 %0, t; }" : "=r"(a) : "l"(p));
    return a;
}
__device__ __forceinline__ unsigned f2tf(float f) {
    unsigned u;
    asm("cvt.rna.tf32.f32 %0, %1;" : "=r"(u) : "f"(f));
    return u;
}
__device__ __forceinline__ void cp16(uint32_t daddr, const void* gptr) {
    asm volatile("cp.async.cg.shared.global [%0], [%1], 16;" :: "r"(daddr), "l"(gptr) : "memory");
}
#define CP_COMMIT() asm volatile("cp.async.commit_group;" ::: "memory")

__device__ __forceinline__ void ldsm4(unsigned r[4], uint32_t addr) {
    asm volatile("ldmatrix.sync.aligned.m8n8.x4.shared.b16 {%0,%1,%2,%3}, [%4];"
                 : "=r"(r[0]), "=r"(r[1]), "=r"(r[2]), "=r"(r[3]) : "r"(addr));
}
__device__ __forceinline__ void mma_tf32(float d[4], const unsigned a[4], const unsigned b[2]) {
    asm volatile(
        "mma.sync.aligned.m16n8k8.row.col.f32.tf32.tf32.f32 "
        "{%0,%1,%2,%3}, {%4,%5,%6,%7}, {%8,%9}, {%0,%1,%2,%3};\n"
        : "+f"(d[0]), "+f"(d[1]), "+f"(d[2]), "+f"(d[3])
        : "r"(a[0]), "r"(a[1]), "r"(a[2]), "r"(a[3]),
          "r"(b[0]), "r"(b[1]));
}
__device__ __forceinline__ uint32_t sw128(uint32_t off) { return off ^ ((off >> 3) & 0x70); }

// ---------------------------------------------------------------------------
// K1: normalize input rows; write tf32-rounded + exact copies, targets as float
// ---------------------------------------------------------------------------
__global__ void k_xnorm(const float* __restrict__ x, const int* __restrict__ tgt,
                        float* __restrict__ out_t) {
    int b = blockIdx.x, t = threadIdx.x;
    float v = x[b * D_NUM + t];
    float ss = v * v;
    #pragma unroll
    for (int o = 16; o; o >>= 1) ss += __shfl_xor_sync(0xffffffffu, ss, o);
    __shared__ float ws[8];
    if ((t & 31) == 0) ws[t >> 5] = ss;
    __syncthreads();
    float tot = 0.f;
    #pragma unroll
    for (int i = 0; i < 8; ++i) tot += ws[i];
    float inv = 1.f / fmaxf(sqrtf(tot), EPSV);
    float xn = v * inv;
    g_xexact[b * D_NUM + t] = xn;
    g_xnorm[b * D_NUM + t] = __uint_as_float(f2tf(xn));
    if (t == 0) out_t[b] = (float)tgt[b];
}

// ---------------------------------------------------------------------------
// K2: per-class inverse norm of W + copy W into new_weight output region
// ---------------------------------------------------------------------------
__global__ void k_winv_copy(const float4* __restrict__ w4, float4* __restrict__ nw4) {
    int gw = (blockIdx.x * blockDim.x + threadIdx.x) >> 5;
    int lane = threadIdx.x & 31;
    if (gw >= C_NUM) return;
    const float4* row = w4 + (size_t)gw * 64;
    float4 a = row[lane];
    float4 b = row[lane + 32];
    float ss = a.x*a.x + a.y*a.y + a.z*a.z + a.w*a.w
             + b.x*b.x + b.y*b.y + b.z*b.z + b.w*b.w;
    #pragma unroll
    for (int o = 16; o; o >>= 1) ss += __shfl_xor_sync(0xffffffffu, ss, o);
    float4* orow = nw4 + (size_t)gw * 64;
    orow[lane] = a;
    orow[lane + 32] = b;
    if (lane == 0) g_winv[gw] = 1.f / fmaxf(sqrtf(ss), EPSV);
}

// ---------------------------------------------------------------------------
// K3: per-class occurrence chains
// ---------------------------------------------------------------------------
__global__ void k_chain(const int* __restrict__ tgt) {
    __shared__ int st[B_NUM];
    int i = threadIdx.x;
    st[i] = tgt[i];
    g_next[i] = -1;
    __syncthreads();
    int prev = -1;
    int me = st[i];
    for (int j = i - 1; j >= 0; --j)
        if (st[j] == me) { prev = j; break; }
    g_head[i] = (prev < 0) ? 1 : 0;
    __syncthreads();
    if (prev >= 0) g_next[prev] = i;
}

// ---------------------------------------------------------------------------
// K4: TF32 mma.sync GEMM, 128x128 tile, BK=32, 3-stage cp.async, ldmatrix frags
// ---------------------------------------------------------------------------
#define NSTG 3
#define STG_BYTES 32768            // A(16KB) + B(16KB) per stage
#define OFF_TILE 1024
#define SMEM_BYTES (OFF_TILE + NSTG * STG_BYTES)

__global__ __launch_bounds__(256, 2)
void k_gemm(const float* __restrict__ W, float* __restrict__ out) {
    extern __shared__ char smem[];
    const uint32_t sb = smem_u32(smem);
    const int tid = threadIdx.x;
    const int lane = tid & 31, warp = tid >> 5;
    const int b0 = blockIdx.x * 128;   // batch tile (x fastest => W L2 reuse)
    const int c0 = blockIdx.y * 128;   // class tile
    const int wm = (warp & 1) * 64;
    const int wn = (warp >> 1) * 32;

    float* winv_s = (float*)smem;      // [128] = 30*winv
    if (tid < 128) {
        int c = c0 + tid; if (c >= C_NUM) c = C_NUM - 1;
        winv_s[tid] = 30.0f * g_winv[c];
    }

    const char* Abase = (const char*)g_xnorm + (size_t)b0 * (D_NUM * 4);
    const char* Bbase = (const char*)W;

    auto issue_load = [&](int stage, int chunk) {
        uint32_t abuf = sb + OFF_TILE + stage * STG_BYTES;
        uint32_t bbuf = abuf + 16384;
        #pragma unroll
        for (int i = 0; i < 4; ++i) {
            int slot = tid + i * 256;
            int r = slot >> 3;
            int sg = (slot & 7) * 16;
            uint32_t so = sw128((uint32_t)(r * 128 + sg));
            cp16(abuf + so, Abase + (size_t)r * 1024 + chunk * 128 + sg);
            int row = c0 + r; if (row >= C_NUM) row = C_NUM - 1;
            cp16(bbuf + so, Bbase + (size_t)row * 1024 + chunk * 128 + sg);
        }
        CP_COMMIT();
    };

    float acc[4][4][4];
    #pragma unroll
    for (int i = 0; i < 4; ++i)
        #pragma unroll
        for (int j = 0; j < 4; ++j)
            #pragma unroll
            for (int r = 0; r < 4; ++r) acc[i][j][r] = 0.f;

    // ldmatrix per-lane offsets (byte offsets within a stage's A / B buffer)
    // A tile i of x4: rows wm+im*16+(lane&15), k-group (lane>>4), per ks add 32B
    uint32_t a_off[4], b_off[2];
    #pragma unroll
    for (int im = 0; im < 4; ++im)
        a_off[im] = (uint32_t)((wm + im * 16 + (lane & 15)) * 128 + ((lane >> 4) << 4));
    #pragma unroll
    for (int jp = 0; jp < 2; ++jp)
        b_off[jp] = (uint32_t)((wn + jp * 16 + ((lane >> 4) << 3) + (lane & 7)) * 128
                               + (((lane >> 3) & 1) << 4));

    issue_load(0, 0);
    issue_load(1, 1);

    for (int c = 0; c < 8; ++c) {
        const int s = c % NSTG;
        if (c + 2 < 8) issue_load((c + 2) % NSTG, c + 2);
        if (c < 6)       asm volatile("cp.async.wait_group 2;" ::: "memory");
        else if (c == 6) asm volatile("cp.async.wait_group 1;" ::: "memory");
        else             asm volatile("cp.async.wait_group 0;" ::: "memory");
        __syncthreads();

        const uint32_t abuf = sb + OFF_TILE + s * STG_BYTES;
        const uint32_t bbuf = abuf + 16384;
        #pragma unroll
        for (int ks = 0; ks < 4; ++ks) {
            unsigned af[4][4], bf[2][4];
            #pragma unroll
            for (int im = 0; im < 4; ++im)
                ldsm4(af[im], abuf + sw128(a_off[im] + ks * 32));
            #pragma unroll
            for (int jp = 0; jp < 2; ++jp)
                ldsm4(bf[jp], bbuf + sw128(b_off[jp] + ks * 32));
            #pragma unroll
            for (int im = 0; im < 4; ++im) {
                #pragma unroll
                for (int jp = 0; jp < 2; ++jp) {
                    mma_tf32(acc[im][jp * 2 + 0], af[im], &bf[jp][0]);
                    mma_tf32(acc[im][jp * 2 + 1], af[im], &bf[jp][2]);
                }
            }
        }
        __syncthreads();   // stage s free for reuse by iteration c+1's issue
    }

    // epilogue: scale by 30*winv, smem transpose, coalesced float4 stores
    float* tb = (float*)(smem + OFF_TILE);   // [128][132]
    const int g4 = lane >> 2, t4 = lane & 3;
    #pragma unroll
    for (int im = 0; im < 4; ++im) {
        int r = wm + im * 16 + g4;
        #pragma unroll
        for (int jn = 0; jn < 4; ++jn) {
            int col = wn + jn * 8 + t4 * 2;
            float s0 = winv_s[col], s1 = winv_s[col + 1];
            *(float2*)&tb[r * 132 + col] =
                make_float2(acc[im][jn][0] * s0, acc[im][jn][1] * s1);
            *(float2*)&tb[(r + 8) * 132 + col] =
                make_float2(acc[im][jn][2] * s0, acc[im][jn][3] * s1);
        }
    }
    __syncthreads();
    #pragma unroll
    for (int it = 0; it < 16; ++it) {
        int r = warp + it * 8;
        int colb = lane * 4;
        float4 val = *(const float4*)&tb[r * 132 + colb];
        int gc = c0 + colb;
        if (gc < C_NUM)
            *(float4*)&out[(size_t)(b0 + r) * C_NUM + gc] = val;
    }
}

// ---------------------------------------------------------------------------
// K5: sequential momentum update per class chain
// ---------------------------------------------------------------------------
__global__ void k_update(const int* __restrict__ tgt, float* __restrict__ nw) {
    int b = blockIdx.x;
    if (!g_head[b]) return;
    int t = threadIdx.x;
    int y = tgt[b];
    float v = nw[(size_t)y * D_NUM + t];
    __shared__ float ws[8];
    int cur = b;
    while (cur >= 0) {
        v = 0.5f * v + 0.5f * g_xexact[cur * D_NUM + t];
        float ss = v * v;
        #pragma unroll
        for (int o = 16; o; o >>= 1) ss += __shfl_xor_sync(0xffffffffu, ss, o);
        __syncthreads();
        if ((t & 31) == 0) ws[t >> 5] = ss;
        __syncthreads();
        float tot = 0.f;
        #pragma unroll
        for (int i = 0; i < 8; ++i) tot += ws[i];
        v *= 1.f / fmaxf(sqrtf(tot), EPSV);
        cur = g_next[cur];
    }
    nw[(size_t)y * D_NUM + t] = v;
}

// ---------------------------------------------------------------------------
extern "C" void kernel_launch(void* const* d_in, const int* in_sizes, int n_in,
                              void* d_out, int out_size) {
    const float* x   = (const float*)d_in[0];
    const int*   tgt = (const int*)d_in[1];
    const float* w   = (const float*)d_in[2];
    float* out      = (float*)d_out;
    float* out_pred = out;                                  // [1024][100000]
    float* out_t    = out + (size_t)B_NUM * C_NUM;          // [1024]
    float* out_nw   = out_t + B_NUM;                        // [100000][256]

    cudaFuncSetAttribute(k_gemm, cudaFuncAttributeMaxDynamicSharedMemorySize, SMEM_BYTES);

    k_xnorm<<<B_NUM, 256>>>(x, tgt, out_t);
    k_winv_copy<<<(C_NUM * 32) / 256, 256>>>((const float4*)w, (float4*)out_nw);
    k_chain<<<1, B_NUM>>>(tgt);
    k_gemm<<<dim3(8, 782), 256, SMEM_BYTES>>>(w, out_pred);
    k_update<<<B_NUM, 256>>>(tgt, out_nw);
}